// round 2
// baseline (speedup 1.0000x reference)
#include <cuda_runtime.h>

#define NB 16
#define NC 512
#define NW 2048

// Scratch (device globals — no allocation allowed)
__device__ float g_f[NB * 128 * 1024];                 // pooled f
__device__ float g_g[NB * 128 * 2048];                 // g
__device__ float g_h[NB * 256 * 1024];                 // pooled h
__device__ float g_s[(size_t)NB * 1024 * 2048];        // s / beta (134 MB)
__device__ float g_o[NB * 256 * 2048];                 // attention output

// ---------------------------------------------------------------------------
// Tiled SGEMM: C[M,N] = A @ B (+bias) with fused epilogues.
// BM=BN=128, BK=16, 256 threads, 8x8 microtile (split 4+4 with stride 64).
// MODE 0: C = A@B + bias
// MODE 1: C = maxpool2_cols(A@B + bias)   (C row stride = N/2)
// MODE 2: C = gamma*(A@B + bias) + X      (residual)
// MODE 3: C = A@B                          (no bias)
// ATRANS: A stored K-major [K, M] (row stride = M) instead of [M, K]
// Requires: M % 128 == 0, N % 128 == 0, K % 16 == 0, rows 16B-aligned.
// ---------------------------------------------------------------------------
template<int MODE, bool ATRANS>
__global__ void __launch_bounds__(256) gemm128(
    const float* __restrict__ A, long long sA,
    const float* __restrict__ B, long long sB,
    float* __restrict__ C, long long sC,
    const float* __restrict__ bias,
    const float* __restrict__ Xres, long long sX,
    const float* __restrict__ gamma,
    int M, int N, int K)
{
    const int BK = 16;
    __shared__ float As[BK][128];
    __shared__ float Bs[BK][128];

    const int bz = blockIdx.z;
    const float* Ab = A + (long long)bz * sA;
    const float* Bb = B + (long long)bz * sB;
    float*       Cb = C + (long long)bz * sC;

    const int m0 = blockIdx.y * 128;
    const int n0 = blockIdx.x * 128;
    const int tid = threadIdx.x;
    const int tx = tid & 15;        // N dim (16)
    const int ty = tid >> 4;        // M dim (16)

    float acc[8][8] = {};

    for (int k0 = 0; k0 < K; k0 += BK) {
        // ---- load A tile into As[k][m] ----
        if (ATRANS) {
            // A is [K, M] row-major: copy 16x128 tile directly
            #pragma unroll
            for (int l = 0; l < 2; l++) {
                int idx = tid + l * 256;          // 0..511
                int r = idx >> 5;                 // k 0..15
                int c4 = (idx & 31) << 2;         // m 0..124
                float4 v = *(const float4*)(Ab + (long long)(k0 + r) * M + m0 + c4);
                *(float4*)&As[r][c4] = v;
            }
        } else {
            // A is [M, K] row-major: load + transpose
            int m = tid >> 1;                     // 0..127
            int kb = (tid & 1) << 3;              // 0 or 8
            #pragma unroll
            for (int l = 0; l < 2; l++) {
                int kk = kb + l * 4;
                float4 v = *(const float4*)(Ab + (long long)(m0 + m) * K + k0 + kk);
                As[kk + 0][m] = v.x;
                As[kk + 1][m] = v.y;
                As[kk + 2][m] = v.z;
                As[kk + 3][m] = v.w;
            }
        }
        // ---- load B tile Bs[k][n] (B is [K, N] row-major) ----
        #pragma unroll
        for (int l = 0; l < 2; l++) {
            int idx = tid + l * 256;
            int r = idx >> 5;                     // k 0..15
            int c4 = (idx & 31) << 2;             // n 0..124
            float4 v = *(const float4*)(Bb + (long long)(k0 + r) * N + n0 + c4);
            *(float4*)&Bs[r][c4] = v;
        }
        __syncthreads();

        #pragma unroll
        for (int kk = 0; kk < BK; kk++) {
            float a[8], b[8];
            float4 a0 = *(const float4*)&As[kk][ty << 2];
            float4 a1 = *(const float4*)&As[kk][64 + (ty << 2)];
            float4 b0 = *(const float4*)&Bs[kk][tx << 2];
            float4 b1 = *(const float4*)&Bs[kk][64 + (tx << 2)];
            a[0]=a0.x; a[1]=a0.y; a[2]=a0.z; a[3]=a0.w;
            a[4]=a1.x; a[5]=a1.y; a[6]=a1.z; a[7]=a1.w;
            b[0]=b0.x; b[1]=b0.y; b[2]=b0.z; b[3]=b0.w;
            b[4]=b1.x; b[5]=b1.y; b[6]=b1.z; b[7]=b1.w;
            #pragma unroll
            for (int i = 0; i < 8; i++)
                #pragma unroll
                for (int j = 0; j < 8; j++)
                    acc[i][j] += a[i] * b[j];
        }
        __syncthreads();
    }

    // Row/col of acc[i][j]:  m = m0 + (i<4 ? ty*4+i : 64+ty*4+i-4)
    //                        n = n0 + (j<4 ? tx*4+j : 64+tx*4+j-4)
    #pragma unroll
    for (int ih = 0; ih < 2; ih++) {
        #pragma unroll
        for (int i = 0; i < 4; i++) {
            const int m = m0 + ih * 64 + (ty << 2) + i;
            const int ii = ih * 4 + i;
            const float bv = (MODE == 0 || MODE == 1 || MODE == 2) ? bias[m] : 0.0f;
            if (MODE == 1) {
                const int Np = N >> 1;
                #pragma unroll
                for (int jh = 0; jh < 2; jh++) {
                    const int n = n0 + jh * 64 + (tx << 2);   // even
                    float p0 = fmaxf(acc[ii][jh*4+0], acc[ii][jh*4+1]) + bv;
                    float p1 = fmaxf(acc[ii][jh*4+2], acc[ii][jh*4+3]) + bv;
                    long long base = (long long)m * Np + (n >> 1);
                    Cb[base + 0] = p0;
                    Cb[base + 1] = p1;
                }
            } else if (MODE == 2) {
                const float* Xb = Xres + (long long)bz * sX;
                const float gm = *gamma;
                #pragma unroll
                for (int jh = 0; jh < 2; jh++) {
                    const int n = n0 + jh * 64 + (tx << 2);
                    #pragma unroll
                    for (int j = 0; j < 4; j++) {
                        long long idx = (long long)m * N + n + j;
                        Cb[idx] = gm * (acc[ii][jh*4+j] + bv) + Xb[idx];
                    }
                }
            } else {
                #pragma unroll
                for (int jh = 0; jh < 2; jh++) {
                    const int n = n0 + jh * 64 + (tx << 2);
                    #pragma unroll
                    for (int j = 0; j < 4; j++) {
                        Cb[(long long)m * N + n + j] = acc[ii][jh*4+j] + bv;
                    }
                }
            }
        }
    }
}

// ---------------------------------------------------------------------------
// Row softmax over N=2048 elements, in place. One block (256 thr) per row.
// ---------------------------------------------------------------------------
__global__ void __launch_bounds__(256) softmax_rows(float* __restrict__ S)
{
    const int N = 2048;
    float* p = S + (long long)blockIdx.x * N;
    const int t = threadIdx.x;

    float v[8];
    float mx = -1e30f;
    #pragma unroll
    for (int j = 0; j < 8; j++) {
        v[j] = p[t + j * 256];
        mx = fmaxf(mx, v[j]);
    }

    __shared__ float red[256];
    red[t] = mx;
    __syncthreads();
    #pragma unroll
    for (int s2 = 128; s2 > 0; s2 >>= 1) {
        if (t < s2) red[t] = fmaxf(red[t], red[t + s2]);
        __syncthreads();
    }
    mx = red[0];
    __syncthreads();

    float sum = 0.0f;
    #pragma unroll
    for (int j = 0; j < 8; j++) {
        v[j] = __expf(v[j] - mx);
        sum += v[j];
    }
    red[t] = sum;
    __syncthreads();
    #pragma unroll
    for (int s2 = 128; s2 > 0; s2 >>= 1) {
        if (t < s2) red[t] += red[t + s2];
        __syncthreads();
    }
    float inv = 1.0f / red[0];

    #pragma unroll
    for (int j = 0; j < 8; j++)
        p[t + j * 256] = v[j] * inv;
}

// ---------------------------------------------------------------------------
extern "C" void kernel_launch(void* const* d_in, const int* in_sizes, int n_in,
                              void* d_out, int out_size)
{
    const float* x     = (const float*)d_in[0];
    const float* wf    = (const float*)d_in[1];
    const float* bf    = (const float*)d_in[2];
    const float* wg    = (const float*)d_in[3];
    const float* bg    = (const float*)d_in[4];
    const float* wh    = (const float*)d_in[5];
    const float* bh    = (const float*)d_in[6];
    const float* wa    = (const float*)d_in[7];
    const float* ba    = (const float*)d_in[8];
    const float* gamma = (const float*)d_in[9];
    float* out = (float*)d_out;

    float *pf, *pg, *ph, *ps, *po;
    cudaGetSymbolAddress((void**)&pf, g_f);
    cudaGetSymbolAddress((void**)&pg, g_g);
    cudaGetSymbolAddress((void**)&ph, g_h);
    cudaGetSymbolAddress((void**)&ps, g_s);
    cudaGetSymbolAddress((void**)&po, g_o);

    const long long sXB = (long long)NC * NW;  // x batch stride

    dim3 blk(256);

    // f = maxpool2(wf@x + bf)   [16,128,1024]
    gemm128<1, false><<<dim3(NW / 128, 128 / 128, NB), blk>>>(
        wf, 0, x, sXB, pf, 128LL * 1024, bf, nullptr, 0, nullptr, 128, NW, NC);

    // g = wg@x + bg             [16,128,2048]
    gemm128<0, false><<<dim3(NW / 128, 128 / 128, NB), blk>>>(
        wg, 0, x, sXB, pg, 128LL * 2048, bg, nullptr, 0, nullptr, 128, NW, NC);

    // h = maxpool2(wh@x + bh)   [16,256,1024]
    gemm128<1, false><<<dim3(NW / 128, 256 / 128, NB), blk>>>(
        wh, 0, x, sXB, ph, 256LL * 1024, bh, nullptr, 0, nullptr, 256, NW, NC);

    // s = f^T @ g               [16,1024,2048]   (A K-major: f is [128,1024])
    gemm128<3, true><<<dim3(NW / 128, 1024 / 128, NB), blk>>>(
        pf, 128LL * 1024, pg, 128LL * 2048, ps, 1024LL * 2048,
        nullptr, nullptr, 0, nullptr, 1024, NW, 128);

    // beta = softmax(s, axis=-1)
    softmax_rows<<<NB * 1024, 256>>>(ps);

    // o = h @ beta              [16,256,2048]
    gemm128<3, false><<<dim3(NW / 128, 256 / 128, NB), blk>>>(
        ph, 256LL * 1024, ps, 1024LL * 2048, po, 256LL * 2048,
        nullptr, nullptr, 0, nullptr, 256, NW, 1024);

    // out = gamma*(wa@o + ba) + x    [16,512,2048]
    gemm128<2, false><<<dim3(NW / 128, 512 / 128, NB), blk>>>(
        wa, 0, po, 256LL * 2048, out, (long long)NC * NW,
        ba, x, sXB, gamma, NC, NW, 256);
}

// round 3
// speedup vs baseline: 2.1065x; 2.1065x over previous
#include <cuda_runtime.h>
#include <cstdint>

#define NB 16
#define NC 512
#define NW 2048

// Scratch (device globals — no allocation allowed)
__device__ float g_f[NB * 128 * 1024];                 // pooled f
__device__ float g_g[NB * 128 * 2048];                 // g
__device__ float g_h[NB * 256 * 1024];                 // pooled h
__device__ float g_s[(size_t)NB * 1024 * 2048];        // s / beta (134 MB)
__device__ float g_o[NB * 256 * 2048];                 // attention output

__device__ __forceinline__ uint32_t f2tf(float f) {
    uint32_t u;
    asm("cvt.rna.tf32.f32 %0, %1;" : "=r"(u) : "f"(f));
    return u;
}

__device__ __forceinline__ void mma_tf32(float c[4], const uint32_t a[4], const uint32_t b[2]) {
    asm volatile(
        "mma.sync.aligned.m16n8k8.row.col.f32.tf32.tf32.f32 "
        "{%0,%1,%2,%3}, {%4,%5,%6,%7}, {%8,%9}, {%0,%1,%2,%3};"
        : "+f"(c[0]), "+f"(c[1]), "+f"(c[2]), "+f"(c[3])
        : "r"(a[0]), "r"(a[1]), "r"(a[2]), "r"(a[3]), "r"(b[0]), "r"(b[1]));
}

// ---------------------------------------------------------------------------
// TF32 tensor-core GEMM: C[M,N] = A @ B (+epilogue).
// Block tile 128x128, BK=16, 256 threads = 8 warps (2 x 4 warp grid),
// warp tile 64x32, mma m16n8k8 (4 mtiles x 4 ntiles per warp).
// MODE 0: C = A@B + bias
// MODE 1: C = maxpool2_cols(A@B + bias)   (C row stride = N/2)
// MODE 2: C = gamma*(A@B + bias) + X      (residual)
// MODE 3: C = A@B                          (no bias)
// ATRANS: A stored K-major [K, M] (row stride = M) instead of [M, K]
// Requires: M % 128 == 0, N % 128 == 0, K % 16 == 0, rows 16B-aligned.
// ---------------------------------------------------------------------------
#define SAP 136   // smem pitch (words); 136 % 32 == 8 -> conflict-free frags

template<int MODE, bool ATRANS>
__global__ void __launch_bounds__(256) gemm_tf32(
    const float* __restrict__ A, long long sA,
    const float* __restrict__ B, long long sB,
    float* __restrict__ C, long long sC,
    const float* __restrict__ bias,
    const float* __restrict__ Xres, long long sX,
    const float* __restrict__ gamma,
    int M, int N, int K)
{
    __shared__ uint32_t As[16 * SAP];
    __shared__ uint32_t Bs[16 * SAP];

    const int bz = blockIdx.z;
    const float* Ab = A + (long long)bz * sA;
    const float* Bb = B + (long long)bz * sB;
    float*       Cb = C + (long long)bz * sC;

    const int m0 = blockIdx.y * 128;
    const int n0 = blockIdx.x * 128;
    const int tid  = threadIdx.x;
    const int lane = tid & 31;
    const int warp = tid >> 5;
    const int wm = warp >> 2;      // 0..1 : 64-row half
    const int wn = warp & 3;       // 0..3 : 32-col slice
    const int grp = lane >> 2;     // 0..7
    const int tig = lane & 3;      // 0..3

    float acc[4][4][4] = {};       // [mtile][ntile][frag]

    for (int k0 = 0; k0 < K; k0 += 16) {
        // ---- load A tile into As[k][m] (tf32) ----
        if (ATRANS) {
            #pragma unroll
            for (int l = 0; l < 2; l++) {
                int idx = tid + l * 256;          // 0..511
                int r   = idx >> 5;               // k 0..15
                int c4  = (idx & 31) << 2;        // m 0..124
                float4 v = *(const float4*)(Ab + (long long)(k0 + r) * M + m0 + c4);
                uint4 u = make_uint4(f2tf(v.x), f2tf(v.y), f2tf(v.z), f2tf(v.w));
                *(uint4*)&As[r * SAP + c4] = u;
            }
        } else {
            int m  = tid >> 1;                    // 0..127
            int kb = (tid & 1) << 3;              // 0 or 8
            #pragma unroll
            for (int l = 0; l < 2; l++) {
                int kk = kb + l * 4;
                float4 v = *(const float4*)(Ab + (long long)(m0 + m) * K + k0 + kk);
                As[(kk + 0) * SAP + m] = f2tf(v.x);
                As[(kk + 1) * SAP + m] = f2tf(v.y);
                As[(kk + 2) * SAP + m] = f2tf(v.z);
                As[(kk + 3) * SAP + m] = f2tf(v.w);
            }
        }
        // ---- load B tile Bs[k][n] (B is [K, N] row-major) ----
        #pragma unroll
        for (int l = 0; l < 2; l++) {
            int idx = tid + l * 256;
            int r   = idx >> 5;
            int c4  = (idx & 31) << 2;
            float4 v = *(const float4*)(Bb + (long long)(k0 + r) * N + n0 + c4);
            uint4 u = make_uint4(f2tf(v.x), f2tf(v.y), f2tf(v.z), f2tf(v.w));
            *(uint4*)&Bs[r * SAP + c4] = u;
        }
        __syncthreads();

        #pragma unroll
        for (int ks = 0; ks < 2; ks++) {
            const int kb = ks * 8;
            uint32_t af[4][4], bf[4][2];
            #pragma unroll
            for (int mt = 0; mt < 4; mt++) {
                const int mB = wm * 64 + mt * 16 + grp;
                af[mt][0] = As[(kb + tig)     * SAP + mB];
                af[mt][1] = As[(kb + tig)     * SAP + mB + 8];
                af[mt][2] = As[(kb + tig + 4) * SAP + mB];
                af[mt][3] = As[(kb + tig + 4) * SAP + mB + 8];
            }
            #pragma unroll
            for (int nt = 0; nt < 4; nt++) {
                const int nB = wn * 32 + nt * 8 + grp;
                bf[nt][0] = Bs[(kb + tig)     * SAP + nB];
                bf[nt][1] = Bs[(kb + tig + 4) * SAP + nB];
            }
            #pragma unroll
            for (int mt = 0; mt < 4; mt++)
                #pragma unroll
                for (int nt = 0; nt < 4; nt++)
                    mma_tf32(acc[mt][nt], af[mt], bf[nt]);
        }
        __syncthreads();
    }

    // ---- epilogue ----
    // acc[mt][nt]: c0 at (r0, cb), c1 at (r0, cb+1), c2 at (r1, cb), c3 at (r1, cb+1)
    // r0 = m0 + wm*64 + mt*16 + grp, r1 = r0 + 8, cb = n0 + wn*32 + nt*8 + tig*2
    #pragma unroll
    for (int mt = 0; mt < 4; mt++) {
        const int r0 = m0 + wm * 64 + mt * 16 + grp;
        const int r1 = r0 + 8;
        const float bv0 = (MODE == 3) ? 0.0f : bias[r0];
        const float bv1 = (MODE == 3) ? 0.0f : bias[r1];
        #pragma unroll
        for (int nt = 0; nt < 4; nt++) {
            const int cb = n0 + wn * 32 + nt * 8 + tig * 2;
            float* a = acc[mt][nt];
            if (MODE == 1) {
                const int Np = N >> 1;
                const int cp = cb >> 1;
                Cb[(long long)r0 * Np + cp] = fmaxf(a[0], a[1]) + bv0;
                Cb[(long long)r1 * Np + cp] = fmaxf(a[2], a[3]) + bv1;
            } else if (MODE == 2) {
                const float* Xb = Xres + (long long)bz * sX;
                const float gm = *gamma;
                long long i0 = (long long)r0 * N + cb;
                long long i1 = (long long)r1 * N + cb;
                float2 x0 = *(const float2*)(Xb + i0);
                float2 x1 = *(const float2*)(Xb + i1);
                float2 o0 = make_float2(gm * (a[0] + bv0) + x0.x, gm * (a[1] + bv0) + x0.y);
                float2 o1 = make_float2(gm * (a[2] + bv1) + x1.x, gm * (a[3] + bv1) + x1.y);
                *(float2*)(Cb + i0) = o0;
                *(float2*)(Cb + i1) = o1;
            } else {
                *(float2*)(Cb + (long long)r0 * N + cb) = make_float2(a[0] + bv0, a[1] + bv0);
                *(float2*)(Cb + (long long)r1 * N + cb) = make_float2(a[2] + bv1, a[3] + bv1);
            }
        }
    }
}

// ---------------------------------------------------------------------------
// Row softmax over N=2048 elements, in place. One block (256 thr) per row.
// ---------------------------------------------------------------------------
__global__ void __launch_bounds__(256) softmax_rows(float* __restrict__ S)
{
    const int N = 2048;
    float* p = S + (long long)blockIdx.x * N;
    const int t = threadIdx.x;

    float v[8];
    float mx = -1e30f;
    #pragma unroll
    for (int j = 0; j < 8; j++) {
        v[j] = p[t + j * 256];
        mx = fmaxf(mx, v[j]);
    }

    __shared__ float red[256];
    red[t] = mx;
    __syncthreads();
    #pragma unroll
    for (int s2 = 128; s2 > 0; s2 >>= 1) {
        if (t < s2) red[t] = fmaxf(red[t], red[t + s2]);
        __syncthreads();
    }
    mx = red[0];
    __syncthreads();

    float sum = 0.0f;
    #pragma unroll
    for (int j = 0; j < 8; j++) {
        v[j] = __expf(v[j] - mx);
        sum += v[j];
    }
    red[t] = sum;
    __syncthreads();
    #pragma unroll
    for (int s2 = 128; s2 > 0; s2 >>= 1) {
        if (t < s2) red[t] += red[t + s2];
        __syncthreads();
    }
    float inv = 1.0f / red[0];

    #pragma unroll
    for (int j = 0; j < 8; j++)
        p[t + j * 256] = v[j] * inv;
}

// ---------------------------------------------------------------------------
extern "C" void kernel_launch(void* const* d_in, const int* in_sizes, int n_in,
                              void* d_out, int out_size)
{
    const float* x     = (const float*)d_in[0];
    const float* wf    = (const float*)d_in[1];
    const float* bf    = (const float*)d_in[2];
    const float* wg    = (const float*)d_in[3];
    const float* bg    = (const float*)d_in[4];
    const float* wh    = (const float*)d_in[5];
    const float* bh    = (const float*)d_in[6];
    const float* wa    = (const float*)d_in[7];
    const float* ba    = (const float*)d_in[8];
    const float* gamma = (const float*)d_in[9];
    float* out = (float*)d_out;

    float *pf, *pg, *ph, *ps, *po;
    cudaGetSymbolAddress((void**)&pf, g_f);
    cudaGetSymbolAddress((void**)&pg, g_g);
    cudaGetSymbolAddress((void**)&ph, g_h);
    cudaGetSymbolAddress((void**)&ps, g_s);
    cudaGetSymbolAddress((void**)&po, g_o);

    const long long sXB = (long long)NC * NW;  // x batch stride

    dim3 blk(256);

    // f = maxpool2(wf@x + bf)   [16,128,1024]
    gemm_tf32<1, false><<<dim3(NW / 128, 1, NB), blk>>>(
        wf, 0, x, sXB, pf, 128LL * 1024, bf, nullptr, 0, nullptr, 128, NW, NC);

    // g = wg@x + bg             [16,128,2048]
    gemm_tf32<0, false><<<dim3(NW / 128, 1, NB), blk>>>(
        wg, 0, x, sXB, pg, 128LL * 2048, bg, nullptr, 0, nullptr, 128, NW, NC);

    // h = maxpool2(wh@x + bh)   [16,256,1024]
    gemm_tf32<1, false><<<dim3(NW / 128, 2, NB), blk>>>(
        wh, 0, x, sXB, ph, 256LL * 1024, bh, nullptr, 0, nullptr, 256, NW, NC);

    // s = f^T @ g               [16,1024,2048]   (A K-major: f is [128,1024])
    gemm_tf32<3, true><<<dim3(NW / 128, 8, NB), blk>>>(
        pf, 128LL * 1024, pg, 128LL * 2048, ps, 1024LL * 2048,
        nullptr, nullptr, 0, nullptr, 1024, NW, 128);

    // beta = softmax(s, axis=-1)
    softmax_rows<<<NB * 1024, 256>>>(ps);

    // o = h @ beta              [16,256,2048]
    gemm_tf32<3, false><<<dim3(NW / 128, 2, NB), blk>>>(
        ph, 256LL * 1024, ps, 1024LL * 2048, po, 256LL * 2048,
        nullptr, nullptr, 0, nullptr, 256, NW, 1024);

    // out = gamma*(wa@o + ba) + x    [16,512,2048]
    gemm_tf32<2, false><<<dim3(NW / 128, 4, NB), blk>>>(
        wa, 0, po, 256LL * 2048, out, (long long)NC * NW,
        ba, x, sXB, gamma, NC, NW, 256);
}

// round 12
// speedup vs baseline: 2.2043x; 1.0464x over previous
#include <cuda_runtime.h>
#include <cstdint>

#define NB 16
#define NC 512
#define NW 2048

// Scratch (device globals — no allocation allowed)
__device__ float g_f[NB * 128 * 1024];                 // pooled f
__device__ float g_g[NB * 128 * 2048];                 // g
__device__ float g_h[NB * 256 * 1024];                 // pooled h
__device__ float g_s[(size_t)NB * 1024 * 2048];        // s (raw scores, 134 MB)
__device__ float g_o[NB * 256 * 2048];                 // attention output
__device__ float g_mx[NB * 1024];                      // softmax row max
__device__ float g_inv[NB * 1024];                     // softmax 1/rowsum

__device__ __forceinline__ uint32_t f2tf(float f) {
    uint32_t u;
    asm("cvt.rna.tf32.f32 %0, %1;" : "=r"(u) : "f"(f));
    return u;
}

__device__ __forceinline__ void mma_tf32(float c[4], const uint32_t a[4], const uint32_t b[2]) {
    asm volatile(
        "mma.sync.aligned.m16n8k8.row.col.f32.tf32.tf32.f32 "
        "{%0,%1,%2,%3}, {%4,%5,%6,%7}, {%8,%9}, {%0,%1,%2,%3};"
        : "+f"(c[0]), "+f"(c[1]), "+f"(c[2]), "+f"(c[3])
        : "r"(a[0]), "r"(a[1]), "r"(a[2]), "r"(a[3]), "r"(b[0]), "r"(b[1]));
}

// ---------------------------------------------------------------------------
// TF32 tensor-core GEMM, double-buffered software pipeline.
// Block tile 128x128, BK=16, 256 threads = 8 warps (2 x 4 warp grid),
// warp tile 64x32, mma m16n8k8 (4 mtiles x 4 ntiles per warp).
// Pipeline per iter: LDG(next) -> MMA(cur buf) -> STS(next, buf^1) -> sync.
// MODE 0: C = A@B + bias
// MODE 1: C = maxpool2_cols(A@B + bias)   (C row stride = N/2)
// MODE 2: C = gamma*(A@B + bias) + X      (residual)
// MODE 3: C = A@B                          (no bias)
// ATRANS: A stored K-major [K, M] (row stride = M) instead of [M, K]
// BEXP:   B rows are raw scores; apply exp(v - Mx[row]) * Inv[row] on load
//         (row = K index; Mx/Inv are per-batch arrays of length K)
// Requires: M % 128 == 0, N % 128 == 0, K % 32 == 0, rows 16B-aligned.
// ---------------------------------------------------------------------------
#define SAP 136   // smem pitch (words); 136 % 32 == 8 -> conflict-free frags

template<int MODE, bool ATRANS, bool BEXP>
__global__ void __launch_bounds__(256) gemm_tf32(
    const float* __restrict__ A, long long sA,
    const float* __restrict__ B, long long sB,
    float* __restrict__ C, long long sC,
    const float* __restrict__ bias,
    const float* __restrict__ Xres, long long sX,
    const float* __restrict__ gamma,
    const float* __restrict__ Mx, const float* __restrict__ Inv,
    int M, int N, int K)
{
    __shared__ uint32_t As[2][16 * SAP];
    __shared__ uint32_t Bs[2][16 * SAP];

    const int bz = blockIdx.z;
    const float* Ab = A + (long long)bz * sA;
    const float* Bb = B + (long long)bz * sB;
    float*       Cb = C + (long long)bz * sC;
    const float* mxb  = BEXP ? Mx  + bz * K : nullptr;
    const float* invb = BEXP ? Inv + bz * K : nullptr;

    const int m0 = blockIdx.y * 128;
    const int n0 = blockIdx.x * 128;
    const int tid  = threadIdx.x;
    const int lane = tid & 31;
    const int warp = tid >> 5;
    const int wm = warp >> 2;      // 0..1 : 64-row half
    const int wn = warp & 3;       // 0..3 : 32-col slice
    const int grp = lane >> 2;     // 0..7
    const int tig = lane & 3;      // 0..3

    // tile-load addressing (constant across iterations)
    const int rB0 = tid >> 5;              // k row for first 256-chunk
    const int cB0 = (tid & 31) << 2;       // col
    const int rB1 = (tid + 256) >> 5;
    const int cB1 = ((tid + 256) & 31) << 2;
    const int mA  = tid >> 1;              // non-trans A: m row
    const int kbA = (tid & 1) << 3;        // non-trans A: k base (0 or 8)

    float4 ra0, ra1, rb0, rb1;             // staging registers

    auto ldgA = [&](int k0) {
        if (ATRANS) {
            ra0 = *(const float4*)(Ab + (long long)(k0 + rB0) * M + m0 + cB0);
            ra1 = *(const float4*)(Ab + (long long)(k0 + rB1) * M + m0 + cB1);
        } else {
            ra0 = *(const float4*)(Ab + (long long)(m0 + mA) * K + k0 + kbA);
            ra1 = *(const float4*)(Ab + (long long)(m0 + mA) * K + k0 + kbA + 4);
        }
    };
    auto ldgB = [&](int k0) {
        rb0 = *(const float4*)(Bb + (long long)(k0 + rB0) * N + n0 + cB0);
        rb1 = *(const float4*)(Bb + (long long)(k0 + rB1) * N + n0 + cB1);
        if (BEXP) {
            float m0v = mxb[k0 + rB0], s0v = invb[k0 + rB0];
            float m1v = mxb[k0 + rB1], s1v = invb[k0 + rB1];
            rb0.x = __expf(rb0.x - m0v) * s0v;
            rb0.y = __expf(rb0.y - m0v) * s0v;
            rb0.z = __expf(rb0.z - m0v) * s0v;
            rb0.w = __expf(rb0.w - m0v) * s0v;
            rb1.x = __expf(rb1.x - m1v) * s1v;
            rb1.y = __expf(rb1.y - m1v) * s1v;
            rb1.z = __expf(rb1.z - m1v) * s1v;
            rb1.w = __expf(rb1.w - m1v) * s1v;
        }
    };
    auto stsA = [&](int buf) {
        uint32_t* S = As[buf];
        if (ATRANS) {
            *(uint4*)&S[rB0 * SAP + cB0] =
                make_uint4(f2tf(ra0.x), f2tf(ra0.y), f2tf(ra0.z), f2tf(ra0.w));
            *(uint4*)&S[rB1 * SAP + cB1] =
                make_uint4(f2tf(ra1.x), f2tf(ra1.y), f2tf(ra1.z), f2tf(ra1.w));
        } else {
            S[(kbA + 0) * SAP + mA] = f2tf(ra0.x);
            S[(kbA + 1) * SAP + mA] = f2tf(ra0.y);
            S[(kbA + 2) * SAP + mA] = f2tf(ra0.z);
            S[(kbA + 3) * SAP + mA] = f2tf(ra0.w);
            S[(kbA + 4) * SAP + mA] = f2tf(ra1.x);
            S[(kbA + 5) * SAP + mA] = f2tf(ra1.y);
            S[(kbA + 6) * SAP + mA] = f2tf(ra1.z);
            S[(kbA + 7) * SAP + mA] = f2tf(ra1.w);
        }
    };
    auto stsB = [&](int buf) {
        uint32_t* S = Bs[buf];
        *(uint4*)&S[rB0 * SAP + cB0] =
            make_uint4(f2tf(rb0.x), f2tf(rb0.y), f2tf(rb0.z), f2tf(rb0.w));
        *(uint4*)&S[rB1 * SAP + cB1] =
            make_uint4(f2tf(rb1.x), f2tf(rb1.y), f2tf(rb1.z), f2tf(rb1.w));
    };

    float acc[4][4][4] = {};       // [mtile][ntile][frag]

    // ---- pipeline prologue ----
    ldgA(0); ldgB(0);
    stsA(0); stsB(0);
    __syncthreads();

    const int nIter = K >> 4;
    for (int i = 0; i < nIter; i++) {
        const bool more = (i + 1) < nIter;
        if (more) { ldgA((i + 1) << 4); ldgB((i + 1) << 4); }

        const int buf = i & 1;
        const uint32_t* SA = As[buf];
        const uint32_t* SB = Bs[buf];
        #pragma unroll
        for (int ks = 0; ks < 2; ks++) {
            const int kb = ks * 8;
            uint32_t af[4][4], bf[4][2];
            #pragma unroll
            for (int mt = 0; mt < 4; mt++) {
                const int mB = wm * 64 + mt * 16 + grp;
                af[mt][0] = SA[(kb + tig)     * SAP + mB];
                af[mt][1] = SA[(kb + tig)     * SAP + mB + 8];
                af[mt][2] = SA[(kb + tig + 4) * SAP + mB];
                af[mt][3] = SA[(kb + tig + 4) * SAP + mB + 8];
            }
            #pragma unroll
            for (int nt = 0; nt < 4; nt++) {
                const int nB = wn * 32 + nt * 8 + grp;
                bf[nt][0] = SB[(kb + tig)     * SAP + nB];
                bf[nt][1] = SB[(kb + tig + 4) * SAP + nB];
            }
            #pragma unroll
            for (int mt = 0; mt < 4; mt++)
                #pragma unroll
                for (int nt = 0; nt < 4; nt++)
                    mma_tf32(acc[mt][nt], af[mt], bf[nt]);
        }

        if (more) {
            stsA(buf ^ 1); stsB(buf ^ 1);
            __syncthreads();
        }
    }

    // ---- epilogue ----
    // acc[mt][nt]: c0 (r0,cb) c1 (r0,cb+1) c2 (r1,cb) c3 (r1,cb+1)
    // r0 = m0 + wm*64 + mt*16 + grp, r1 = r0 + 8, cb = n0 + wn*32 + nt*8 + tig*2
    #pragma unroll
    for (int mt = 0; mt < 4; mt++) {
        const int r0 = m0 + wm * 64 + mt * 16 + grp;
        const int r1 = r0 + 8;
        const float bv0 = (MODE == 3) ? 0.0f : bias[r0];
        const float bv1 = (MODE == 3) ? 0.0f : bias[r1];
        #pragma unroll
        for (int nt = 0; nt < 4; nt++) {
            const int cb = n0 + wn * 32 + nt * 8 + tig * 2;
            float* a = acc[mt][nt];
            if (MODE == 1) {
                const int Np = N >> 1;
                const int cp = cb >> 1;
                Cb[(long long)r0 * Np + cp] = fmaxf(a[0], a[1]) + bv0;
                Cb[(long long)r1 * Np + cp] = fmaxf(a[2], a[3]) + bv1;
            } else if (MODE == 2) {
                const float* Xb = Xres + (long long)bz * sX;
                const float gm = *gamma;
                long long i0 = (long long)r0 * N + cb;
                long long i1 = (long long)r1 * N + cb;
                float2 x0 = *(const float2*)(Xb + i0);
                float2 x1 = *(const float2*)(Xb + i1);
                *(float2*)(Cb + i0) = make_float2(gm * (a[0] + bv0) + x0.x,
                                                  gm * (a[1] + bv0) + x0.y);
                *(float2*)(Cb + i1) = make_float2(gm * (a[2] + bv1) + x1.x,
                                                  gm * (a[3] + bv1) + x1.y);
            } else {
                *(float2*)(Cb + (long long)r0 * N + cb) = make_float2(a[0] + bv0, a[1] + bv0);
                *(float2*)(Cb + (long long)r1 * N + cb) = make_float2(a[2] + bv1, a[3] + bv1);
            }
        }
    }
}

// ---------------------------------------------------------------------------
// Softmax stats: per row of S (N=2048), compute max and 1/sum(exp(v-max)).
// One block (256 thr) per row. Read-only on S.
// ---------------------------------------------------------------------------
__global__ void __launch_bounds__(256) softmax_stats(
    const float* __restrict__ S, float* __restrict__ Mx, float* __restrict__ Inv)
{
    const int N = 2048;
    const float* p = S + (long long)blockIdx.x * N;
    const int t = threadIdx.x;

    float4 v0 = *(const float4*)(p + t * 4);
    float4 v1 = *(const float4*)(p + 1024 + t * 4);
    float mx = fmaxf(fmaxf(fmaxf(v0.x, v0.y), fmaxf(v0.z, v0.w)),
                     fmaxf(fmaxf(v1.x, v1.y), fmaxf(v1.z, v1.w)));

    __shared__ float red[256];
    red[t] = mx;
    __syncthreads();
    #pragma unroll
    for (int s2 = 128; s2 > 0; s2 >>= 1) {
        if (t < s2) red[t] = fmaxf(red[t], red[t + s2]);
        __syncthreads();
    }
    mx = red[0];
    __syncthreads();

    float sum = __expf(v0.x - mx) + __expf(v0.y - mx) + __expf(v0.z - mx) + __expf(v0.w - mx)
              + __expf(v1.x - mx) + __expf(v1.y - mx) + __expf(v1.z - mx) + __expf(v1.w - mx);

    red[t] = sum;
    __syncthreads();
    #pragma unroll
    for (int s2 = 128; s2 > 0; s2 >>= 1) {
        if (t < s2) red[t] += red[t + s2];
        __syncthreads();
    }
    if (t == 0) {
        Mx[blockIdx.x]  = mx;
        Inv[blockIdx.x] = 1.0f / red[0];
    }
}

// ---------------------------------------------------------------------------
extern "C" void kernel_launch(void* const* d_in, const int* in_sizes, int n_in,
                              void* d_out, int out_size)
{
    const float* x     = (const float*)d_in[0];
    const float* wf    = (const float*)d_in[1];
    const float* bf    = (const float*)d_in[2];
    const float* wg    = (const float*)d_in[3];
    const float* bg    = (const float*)d_in[4];
    const float* wh    = (const float*)d_in[5];
    const float* bh    = (const float*)d_in[6];
    const float* wa    = (const float*)d_in[7];
    const float* ba    = (const float*)d_in[8];
    const float* gamma = (const float*)d_in[9];
    float* out = (float*)d_out;

    float *pf, *pg, *ph, *ps, *po, *pmx, *pinv;
    cudaGetSymbolAddress((void**)&pf, g_f);
    cudaGetSymbolAddress((void**)&pg, g_g);
    cudaGetSymbolAddress((void**)&ph, g_h);
    cudaGetSymbolAddress((void**)&ps, g_s);
    cudaGetSymbolAddress((void**)&po, g_o);
    cudaGetSymbolAddress((void**)&pmx, g_mx);
    cudaGetSymbolAddress((void**)&pinv, g_inv);

    const long long sXB = (long long)NC * NW;  // x batch stride

    dim3 blk(256);

    // f = maxpool2(wf@x + bf)   [16,128,1024]
    gemm_tf32<1, false, false><<<dim3(NW / 128, 1, NB), blk>>>(
        wf, 0, x, sXB, pf, 128LL * 1024, bf, nullptr, 0, nullptr,
        nullptr, nullptr, 128, NW, NC);

    // g = wg@x + bg             [16,128,2048]
    gemm_tf32<0, false, false><<<dim3(NW / 128, 1, NB), blk>>>(
        wg, 0, x, sXB, pg, 128LL * 2048, bg, nullptr, 0, nullptr,
        nullptr, nullptr, 128, NW, NC);

    // h = maxpool2(wh@x + bh)   [16,256,1024]
    gemm_tf32<1, false, false><<<dim3(NW / 128, 2, NB), blk>>>(
        wh, 0, x, sXB, ph, 256LL * 1024, bh, nullptr, 0, nullptr,
        nullptr, nullptr, 256, NW, NC);

    // s = f^T @ g               [16,1024,2048]   (A K-major: f is [128,1024])
    gemm_tf32<3, true, false><<<dim3(NW / 128, 8, NB), blk>>>(
        pf, 128LL * 1024, pg, 128LL * 2048, ps, 1024LL * 2048,
        nullptr, nullptr, 0, nullptr, nullptr, nullptr, 1024, NW, 128);

    // softmax stats: per-row max and 1/sum over s
    softmax_stats<<<NB * 1024, 256>>>(ps, pmx, pinv);

    // o = h @ softmax(s)        [16,256,2048]  (exp applied on B load)
    gemm_tf32<3, false, true><<<dim3(NW / 128, 2, NB), blk>>>(
        ph, 256LL * 1024, ps, 1024LL * 2048, po, 256LL * 2048,
        nullptr, nullptr, 0, nullptr, pmx, pinv, 256, NW, 1024);

    // out = gamma*(wa@o + ba) + x    [16,512,2048]
    gemm_tf32<2, false, false><<<dim3(NW / 128, 4, NB), blk>>>(
        wa, 0, po, 256LL * 2048, out, (long long)NC * NW,
        ba, x, sXB, gamma, nullptr, nullptr, NC, NW, 256);
}